// round 13
// baseline (speedup 1.0000x reference)
#include <cuda_runtime.h>
#include <math.h>

#define N_NODES 10000
#define N_EDGES 160000
#define NSC 128
#define NVC 64
#define LATD 64
#define EPSLN 1e-5f
#define INV_SQ3 0.57735026918962576f
#define INV_SQ2 0.70710678118654752f

typedef unsigned long long u64;

// packed f32x2 helpers (FFMA2 path — only reachable via PTX)
__device__ __forceinline__ u64 pk2(float w) {
    u64 r; asm("mov.b64 %0, {%1, %1};" : "=l"(r) : "f"(w)); return r;
}
__device__ __forceinline__ void fma2(u64& acc, u64 a, u64 b) {
    asm("fma.rn.f32x2 %0, %1, %2, %0;" : "+l"(acc) : "l"(a), "l"(b));
}
__device__ __forceinline__ void mul2(u64& a, u64 b) {
    asm("mul.rn.f32x2 %0, %0, %1;" : "+l"(a) : "l"(b));
}
__device__ __forceinline__ float2 up(u64 v) {
    union { u64 u; float2 f; } x; x.u = v; return x.f;
}
__device__ __forceinline__ void un4(const u64* p, float* f) {
    float2 a = up(p[0]), b = up(p[1]);
    f[0] = a.x; f[1] = a.y; f[2] = b.x; f[3] = b.y;
}

// scratch: LayerNormed node features
__device__ float g_ns[N_NODES * NSC];       // 5.12 MB
__device__ float g_nv[N_NODES * NVC * 3];   // 7.68 MB

// packed weight scratch (filled by prep blocks of node_kernel each launch)
__device__ float4 w_ss0p[256 * 64];   // (Wss0[k][j], [64+j], [128+j], 0)
__device__ float4 w_vv0p[128 * 64];   // same for Wvv0
__device__ float4 w_envp[64 * 64];    // same for Wenv
__device__ float4 w_sv1q[64 * 64];    // (Wsv1[4k..4k+3][f])
__device__ float4 w_psq[64 * 64];     // (Wps[2k][j], Wps[2k][64+j], Wps[2k+1][j], Wps[2k+1][64+j])
__device__ float4 w_vsvvq[64 * 64];   // (Wvs1[2c][f], Wvv1[2c][f], Wvs1[2c+1][f], Wvv1[2c+1][f])
__device__ float4 w_pvq[16 * 64];     // (Wpv[4k..4k+3][f])

__device__ __forceinline__ float brsum(float v, volatile float* red, int t) {
#pragma unroll
    for (int o = 16; o; o >>= 1) v += __shfl_xor_sync(0xffffffffu, v, o);
    __syncthreads();
    if ((t & 31) == 0) red[t >> 5] = v;
    __syncthreads();
    return red[0] + red[1] + red[2] + red[3];
}

// ---------------------------------------------------------------------------
// Node kernel (blocks 0..295): separable LN -> g_ns/g_nv, residual -> out
// Prep blocks (296..423): pack weights into __device__ scratch
// ---------------------------------------------------------------------------
__global__ void __launch_bounds__(128, 2) node_kernel(
    const float* __restrict__ nf,
    const float* __restrict__ gsn, const float* __restrict__ bsn,
    const float* __restrict__ gvn,
    const float* __restrict__ Wrs, const float* __restrict__ Wrv,
    const float* __restrict__ Wss0, const float* __restrict__ Wvv0,
    const float* __restrict__ Wenv, const float* __restrict__ Wps,
    const float* __restrict__ Wvs1, const float* __restrict__ Wvv1,
    const float* __restrict__ Wsv1, const float* __restrict__ Wpv,
    float* __restrict__ out)
{
    if (blockIdx.x >= 296) {
        // ---- weight prep path ----
        int i = (blockIdx.x - 296) * 128 + threadIdx.x;   // 0..16383
        int k = i >> 6, j = i & 63;
        w_ss0p[i] = make_float4(Wss0[k * 192 + j], Wss0[k * 192 + 64 + j],
                                Wss0[k * 192 + 128 + j], 0.f);
        if (k < 128) {
            w_vv0p[i] = make_float4(Wvv0[k * 192 + j], Wvv0[k * 192 + 64 + j],
                                    Wvv0[k * 192 + 128 + j], 0.f);
        }
        if (k < 64) {
            w_envp[i] = make_float4(Wenv[k * 192 + j], Wenv[k * 192 + 64 + j],
                                    Wenv[k * 192 + 128 + j], 0.f);
            w_sv1q[i] = make_float4(Wsv1[(4 * k) * 64 + j], Wsv1[(4 * k + 1) * 64 + j],
                                    Wsv1[(4 * k + 2) * 64 + j], Wsv1[(4 * k + 3) * 64 + j]);
            w_psq[i]  = make_float4(Wps[(2 * k) * 128 + j], Wps[(2 * k) * 128 + 64 + j],
                                    Wps[(2 * k + 1) * 128 + j], Wps[(2 * k + 1) * 128 + 64 + j]);
            w_vsvvq[i] = make_float4(Wvs1[(2 * k) * 64 + j], Wvv1[(2 * k) * 64 + j],
                                     Wvs1[(2 * k + 1) * 64 + j], Wvv1[(2 * k + 1) * 64 + j]);
        }
        if (k < 16)
            w_pvq[i] = make_float4(Wpv[(4 * k) * 64 + j], Wpv[(4 * k + 1) * 64 + j],
                                   Wpv[(4 * k + 2) * 64 + j], Wpv[(4 * k + 3) * 64 + j]);
        return;
    }

    extern __shared__ float sm[];
    float* wS  = sm;             // 128*128
    float* wV  = sm + 16384;     // 64*64
    float* sb  = sm + 20480;     // 320
    float* red = sm + 20800;     // 8
    const int t = threadIdx.x;

    for (int i = t; i < 16384; i += 128) wS[i] = Wrs[i];
    for (int i = t; i < 4096;  i += 128) wV[i] = Wrv[i];
    __syncthreads();

    for (int n = blockIdx.x; n < N_NODES; n += 296) {
        const float* row = nf + n * 320;
        sb[t] = row[t];
        sb[128 + t] = row[128 + t];
        if (t < 64) sb[256 + t] = row[256 + t];
        __syncthreads();

        float x = sb[t];
        float ssum = brsum(x, red, t);
        float ssq  = brsum(x * x, red, t);
        float mu = ssum * (1.f / 128.f);
        float var = ssq * (1.f / 128.f) - mu * mu;
        float rsg = rsqrtf(var + EPSLN);
        g_ns[n * NSC + t] = (x - mu) * rsg * gsn[t] + bsn[t];

        float v1 = sb[128 + t];
        float v2 = (t < 64) ? sb[256 + t] : 0.f;
        float vq = brsum(v1 * v1 + v2 * v2, red, t);
        float vsc = rsqrtf(vq * (1.f / 64.f) + EPSLN);
        g_nv[n * 192 + t] = v1 * vsc * gvn[t / 3];
        if (t < 64) g_nv[n * 192 + 128 + t] = v2 * vsc * gvn[(128 + t) / 3];

        float acc = 0.f;
#pragma unroll 8
        for (int k = 0; k < 128; k++) acc += sb[k] * wS[k * 128 + t];
        out[n * 320 + t] = acc;

        {
            int f = t & 63, d = t >> 6;
            float a = 0.f;
#pragma unroll 8
            for (int c = 0; c < 64; c++) a += sb[128 + c * 3 + d] * wV[c * 64 + f];
            out[n * 320 + 128 + f * 3 + d] = a;
        }
        if (t < 64) {
            float a = 0.f;
#pragma unroll 8
            for (int c = 0; c < 64; c++) a += sb[128 + c * 3 + 2] * wV[c * 64 + t];
            out[n * 320 + 128 + t * 3 + 2] = a;
        }
        __syncthreads();
    }
}

// ---------------------------------------------------------------------------
// Edge kernel: 16 edges/block, 256 threads, 2 CTAs/SM, packed-f32x2 GEMMs,
// k-split stage 2, register-carried t1/env-w, 4 block barriers total
// ---------------------------------------------------------------------------
#define ST 20
#define NQ2 5                  // ulonglong2 (16B) per row
#define OFF_S    0             // [256][20]
#define OFF_V    5120          // [384][20]
#define OFF_DOT  12800         // [128][20]
#define OFF_O0   15360         // [192][20]
#define OFF_OV   19200         // [192][20]
#define OFF_LAT  23040         // [64][20]
#define OFF_SH   24320         // [4][20]
#define OFF_GSE  24400
#define OFF_BSE  24528
#define OFF_GVE  24656
#define OFF_C    24720         // 16 ints
#define SMEM_EDGE_FLOATS 24736

__global__ void __launch_bounds__(256, 2) edge_kernel(
    const float* __restrict__ latents, const float* __restrict__ ef,
    const float* __restrict__ esh, const int* __restrict__ eidx,
    const int* __restrict__ act,
    const float* __restrict__ gse, const float* __restrict__ bse,
    const float* __restrict__ gve,
    float* __restrict__ out)
{
    extern __shared__ float sm[];
    float* sS   = sm + OFF_S;
    float* sV   = sm + OFF_V;
    float* sDot = sm + OFF_DOT;
    float* sO0  = sm + OFF_O0;
    float* sOV  = sm + OFF_OV;
    float* sLat = sm + OFF_LAT;
    float* sSh  = sm + OFF_SH;
    float* pGse = sm + OFF_GSE;
    float* pBse = sm + OFF_BSE;
    float* pGve = sm + OFF_GVE;
    int*   sC   = (int*)(sm + OFF_C);

    const int t = threadIdx.x;

    if (t < 128) { pGse[t] = gse[t]; pBse[t] = bse[t]; }
    else if (t < 192) { pGve[t - 128] = gve[t - 128]; }
    __syncthreads();

    // ---- Phase A: gather + edge LN + warp-local dotV + zero sO0 ----
    {
        const int lane = t & 31;
        const int e = ((t >> 5) * 2) + (lane >> 4), l = lane & 15;
        const int eg = blockIdx.x * 16 + e;
        const int ae = act[eg];
        const int c  = eidx[ae];
        if (l == 0) {
            sC[e] = c;
            sSh[0 * ST + e] = esh[eg * 4 + 0];
            sSh[1 * ST + e] = esh[eg * 4 + 1];
            sSh[2 * ST + e] = esh[eg * 4 + 2];
            sSh[3 * ST + e] = esh[eg * 4 + 3];
        }
        {
            const float4* lq = (const float4*)(latents + (size_t)ae * 64);
            float4 v = lq[l];
            sLat[(4 * l + 0) * ST + e] = v.x;
            sLat[(4 * l + 1) * ST + e] = v.y;
            sLat[(4 * l + 2) * ST + e] = v.z;
            sLat[(4 * l + 3) * ST + e] = v.w;
        }
        {
            const float4* nq = (const float4*)(g_ns + (size_t)c * 128);
            float4 a = nq[l], b = nq[l + 16];
#pragma unroll
            for (int s = 0; s < 4; s++) {
                sS[(4 * l + s) * ST + e]      = ((const float*)&a)[s];
                sS[(64 + 4 * l + s) * ST + e] = ((const float*)&b)[s];
            }
        }
        {
            const float4* nq = (const float4*)(g_nv + (size_t)c * 192);
            float4 a = nq[l], b = nq[l + 16], cc4 = nq[l + 32];
#pragma unroll
            for (int s = 0; s < 4; s++) {
                sV[(4 * l + s) * ST + e]       = ((const float*)&a)[s];
                sV[(64 + 4 * l + s) * ST + e]  = ((const float*)&b)[s];
                sV[(128 + 4 * l + s) * ST + e] = ((const float*)&cc4)[s];
            }
        }
        const float4* eq = (const float4*)(ef + (size_t)eg * 320);
        float4 ra = eq[l], rb = eq[l + 16];
        float sum = ra.x + ra.y + ra.z + ra.w + rb.x + rb.y + rb.z + rb.w;
        float ssq = ra.x*ra.x + ra.y*ra.y + ra.z*ra.z + ra.w*ra.w
                  + rb.x*rb.x + rb.y*rb.y + rb.z*rb.z + rb.w*rb.w;
#pragma unroll
        for (int o = 1; o < 16; o <<= 1) {
            sum += __shfl_xor_sync(0xffffffffu, sum, o);
            ssq += __shfl_xor_sync(0xffffffffu, ssq, o);
        }
        float mu  = sum * (1.f / 128.f);
        float var = ssq * (1.f / 128.f) - mu * mu;
        float rsg = rsqrtf(var + EPSLN);
#pragma unroll
        for (int s = 0; s < 4; s++) {
            int j0 = 4 * l + s, j1 = 64 + 4 * l + s;
            sS[(128 + j0) * ST + e] = (((const float*)&ra)[s] - mu) * rsg * pGse[j0] + pBse[j0];
            sS[(128 + j1) * ST + e] = (((const float*)&rb)[s] - mu) * rsg * pGse[j1] + pBse[j1];
        }
        float4 va = eq[32 + l], vb = eq[48 + l], vc = eq[64 + l];
        float sv2 = va.x*va.x + va.y*va.y + va.z*va.z + va.w*va.w
                  + vb.x*vb.x + vb.y*vb.y + vb.z*vb.z + vb.w*vb.w
                  + vc.x*vc.x + vc.y*vc.y + vc.z*vc.z + vc.w*vc.w;
#pragma unroll
        for (int o = 1; o < 16; o <<= 1)
            sv2 += __shfl_xor_sync(0xffffffffu, sv2, o);
        float vsc = rsqrtf(sv2 * (1.f / 64.f) + EPSLN);
#pragma unroll
        for (int s = 0; s < 4; s++) {
            int i0 = 4 * l + s, i1 = 64 + 4 * l + s, i2 = 128 + 4 * l + s;
            sV[(192 + i0) * ST + e] = ((const float*)&va)[s] * vsc * pGve[i0 / 3];
            sV[(192 + i1) * ST + e] = ((const float*)&vb)[s] * vsc * pGve[i1 / 3];
            sV[(192 + i2) * ST + e] = ((const float*)&vc)[s] * vsc * pGve[i2 / 3];
        }

        // warp-local dotV: edge e lives entirely in this warp.
        // 16 lanes x 8 channels = all 128 channels (64 node + 64 edge).
        __syncwarp();
        float shx = sSh[1 * ST + e], shy = sSh[2 * ST + e], shz = sSh[3 * ST + e];
#pragma unroll
        for (int s = 0; s < 8; s++) {
            int cc = 8 * l + s;
            sDot[cc * ST + e] =
                (sV[(3 * cc + 0) * ST + e] * shx +
                 sV[(3 * cc + 1) * ST + e] * shy +
                 sV[(3 * cc + 2) * ST + e] * shz) * INV_SQ3;
        }
        // zero sO0 for stage-2 reduction
        for (int i = t; i < 192 * ST; i += 256) sO0[i] = 0.f;
    }
    __syncthreads();

    const ulonglong2* sS2  = (const ulonglong2*)sS;
    const ulonglong2* sD2  = (const ulonglong2*)sDot;
    const ulonglong2* sL2  = (const ulonglong2*)sLat;
    const ulonglong2* sV2  = (const ulonglong2*)sV;
    const ulonglong2* sO02 = (const ulonglong2*)sO0;
    const ulonglong2* sOV2 = (const ulonglong2*)sOV;

    // ---- Phase C: out0 = sh0*(S@Wss0) + dot@Wvv0, k-split across groups ----
    {
        const int jj = t & 63, grp = t >> 6;
        u64 acc[3][8];
#pragma unroll
        for (int c = 0; c < 3; c++)
#pragma unroll
            for (int p = 0; p < 8; p++) acc[c][p] = 0;

#pragma unroll 2
        for (int k = grp * 64; k < grp * 64 + 64; k++) {
            ulonglong2 q0 = sS2[k * NQ2 + 0], q1 = sS2[k * NQ2 + 1];
            ulonglong2 q2 = sS2[k * NQ2 + 2], q3 = sS2[k * NQ2 + 3];
            float4 w = w_ss0p[k * 64 + jj];
            u64 W0 = pk2(w.x), W1 = pk2(w.y), W2 = pk2(w.z);
            u64 A[8] = {q0.x, q0.y, q1.x, q1.y, q2.x, q2.y, q3.x, q3.y};
#pragma unroll
            for (int p = 0; p < 8; p++) {
                fma2(acc[0][p], A[p], W0);
                fma2(acc[1][p], A[p], W1);
                fma2(acc[2][p], A[p], W2);
            }
        }
        {
            const ulonglong2* sh0q = (const ulonglong2*)&sSh[0];
            ulonglong2 s0 = sh0q[0], s1 = sh0q[1], s2 = sh0q[2], s3 = sh0q[3];
            u64 S[8] = {s0.x, s0.y, s1.x, s1.y, s2.x, s2.y, s3.x, s3.y};
#pragma unroll
            for (int c = 0; c < 3; c++)
#pragma unroll
                for (int p = 0; p < 8; p++) mul2(acc[c][p], S[p]);
        }
#pragma unroll 2
        for (int k = grp * 32; k < grp * 32 + 32; k++) {
            ulonglong2 q0 = sD2[k * NQ2 + 0], q1 = sD2[k * NQ2 + 1];
            ulonglong2 q2 = sD2[k * NQ2 + 2], q3 = sD2[k * NQ2 + 3];
            float4 w = w_vv0p[k * 64 + jj];
            u64 W0 = pk2(w.x), W1 = pk2(w.y), W2 = pk2(w.z);
            u64 A[8] = {q0.x, q0.y, q1.x, q1.y, q2.x, q2.y, q3.x, q3.y};
#pragma unroll
            for (int p = 0; p < 8; p++) {
                fma2(acc[0][p], A[p], W0);
                fma2(acc[1][p], A[p], W1);
                fma2(acc[2][p], A[p], W2);
            }
        }
#pragma unroll
        for (int c = 0; c < 3; c++) {
            int col = jj + c * 64;
#pragma unroll
            for (int p = 0; p < 8; p++) {
                float2 v = up(acc[c][p]);
                atomicAdd(&sO0[col * ST + 2 * p],     v.x);
                atomicAdd(&sO0[col * ST + 2 * p + 1], v.y);
            }
        }
    }
    __syncthreads();

    // ---- Phase D: S3 (t1->regs) + 4b (env w->regs) + 4a silu + 4c ----
    float t1r[4], w0r[4], w1r[4], w2r[4];
    {
        const int f = t & 63, egp = t >> 6;
        // S3: t1 = S @ Wsv1 (quad k), stays in registers
        {
            u64 acc[2] = {0, 0};
#pragma unroll 4
            for (int kk = 0; kk < 64; kk++) {
                float4 w = w_sv1q[kk * 64 + f];
                ulonglong2 a0 = sS2[(4 * kk + 0) * NQ2 + egp];
                ulonglong2 a1 = sS2[(4 * kk + 1) * NQ2 + egp];
                ulonglong2 a2 = sS2[(4 * kk + 2) * NQ2 + egp];
                ulonglong2 a3 = sS2[(4 * kk + 3) * NQ2 + egp];
                u64 W0 = pk2(w.x), W1 = pk2(w.y), W2 = pk2(w.z), W3 = pk2(w.w);
                fma2(acc[0], a0.x, W0); fma2(acc[1], a0.y, W0);
                fma2(acc[0], a1.x, W1); fma2(acc[1], a1.y, W1);
                fma2(acc[0], a2.x, W2); fma2(acc[1], a2.y, W2);
                fma2(acc[0], a3.x, W3); fma2(acc[1], a3.y, W3);
            }
            un4(acc, t1r);
        }
        // 4b: w = lat @ Wenv, stays in registers
        {
            u64 a0[2] = {0,0}, a1[2] = {0,0}, a2[2] = {0,0};
#pragma unroll 4
            for (int k = 0; k < 64; k++) {
                ulonglong2 a = sL2[k * NQ2 + egp];
                float4 w = w_envp[k * 64 + f];
                u64 W0 = pk2(w.x), W1 = pk2(w.y), W2 = pk2(w.z);
                fma2(a0[0], a.x, W0); fma2(a0[1], a.y, W0);
                fma2(a1[0], a.x, W1); fma2(a1[1], a.y, W1);
                fma2(a2[0], a.x, W2); fma2(a2[1], a.y, W2);
            }
            un4(a0, w0r); un4(a1, w1r); un4(a2, w2r);
        }
        // 4a: silu in place on rows 0..127 of sO0 (disjoint from 4c's reads)
        {
            const int e = t & 15;
#pragma unroll
            for (int it = 0; it < 8; it++) {
                int j = (t >> 4) + 16 * it;
                float x = sO0[j * ST + e];
                sO0[j * ST + e] = x / (1.f + __expf(-x));
            }
        }
        // 4c: vector path (cross folded into epilogue, paired c)
        {
            u64 pAx[2]={0,0}, pAy[2]={0,0}, pAz[2]={0,0};
            u64 pBx[2]={0,0}, pBy[2]={0,0}, pBz[2]={0,0};
#pragma unroll 2
            for (int c2 = 0; c2 < 64; c2++) {
                float4 w = w_vsvvq[c2 * 64 + f];
                {
                    int c = 2 * c2;
                    ulonglong2 vx = sV2[(c * 3 + 0) * NQ2 + egp];
                    ulonglong2 vy = sV2[(c * 3 + 1) * NQ2 + egp];
                    ulonglong2 vz = sV2[(c * 3 + 2) * NQ2 + egp];
                    u64 W1 = pk2(w.x), W2 = pk2(w.y);
                    fma2(pAx[0], vx.x, W1); fma2(pAx[1], vx.y, W1);
                    fma2(pAy[0], vy.x, W1); fma2(pAy[1], vy.y, W1);
                    fma2(pAz[0], vz.x, W1); fma2(pAz[1], vz.y, W1);
                    fma2(pBx[0], vx.x, W2); fma2(pBx[1], vx.y, W2);
                    fma2(pBy[0], vy.x, W2); fma2(pBy[1], vy.y, W2);
                    fma2(pBz[0], vz.x, W2); fma2(pBz[1], vz.y, W2);
                }
                {
                    int c = 2 * c2 + 1;
                    ulonglong2 vx = sV2[(c * 3 + 0) * NQ2 + egp];
                    ulonglong2 vy = sV2[(c * 3 + 1) * NQ2 + egp];
                    ulonglong2 vz = sV2[(c * 3 + 2) * NQ2 + egp];
                    u64 W1 = pk2(w.z), W2 = pk2(w.w);
                    fma2(pAx[0], vx.x, W1); fma2(pAx[1], vx.y, W1);
                    fma2(pAy[0], vy.x, W1); fma2(pAy[1], vy.y, W1);
                    fma2(pAz[0], vz.x, W1); fma2(pAz[1], vz.y, W1);
                    fma2(pBx[0], vx.x, W2); fma2(pBx[1], vx.y, W2);
                    fma2(pBy[0], vy.x, W2); fma2(pBy[1], vy.y, W2);
                    fma2(pBz[0], vz.x, W2); fma2(pBz[1], vz.y, W2);
                }
            }
            float Ax[4], Ay[4], Az[4], Bx[4], By[4], Bz[4];
            un4(pAx, Ax); un4(pAy, Ay); un4(pAz, Az);
            un4(pBx, Bx); un4(pBy, By); un4(pBz, Bz);
            float4 s0 = *(const float4*)&sSh[0 * ST + egp * 4];
            float4 sx = *(const float4*)&sSh[1 * ST + egp * 4];
            float4 sy = *(const float4*)&sSh[2 * ST + egp * 4];
            float4 sz = *(const float4*)&sSh[3 * ST + egp * 4];
            float4 gg = *(const float4*)&sO0[(128 + f) * ST + egp * 4];
            float4 ox, oy, oz;
#pragma unroll
            for (int s = 0; s < 4; s++) {
                float g = 1.f / (1.f + __expf(-((const float*)&gg)[s]));
                float cx = (By[s] * ((const float*)&sz)[s] - Bz[s] * ((const float*)&sy)[s]) * INV_SQ2;
                float cy = (Bz[s] * ((const float*)&sx)[s] - Bx[s] * ((const float*)&sz)[s]) * INV_SQ2;
                float cz = (Bx[s] * ((const float*)&sy)[s] - By[s] * ((const float*)&sx)[s]) * INV_SQ2;
                float t1v = t1r[s];
                float s0v = ((const float*)&s0)[s];
                ((float*)&ox)[s] = g * (s0v * Ax[s] + cx + t1v * ((const float*)&sx)[s]);
                ((float*)&oy)[s] = g * (s0v * Ay[s] + cy + t1v * ((const float*)&sy)[s]);
                ((float*)&oz)[s] = g * (s0v * Az[s] + cz + t1v * ((const float*)&sz)[s]);
            }
            *(float4*)&sOV[(f * 3 + 0) * ST + egp * 4] = ox;
            *(float4*)&sOV[(f * 3 + 1) * ST + egp * 4] = oy;
            *(float4*)&sOV[(f * 3 + 2) * ST + egp * 4] = oz;
        }
    }
    __syncthreads();

    // ---- Phase E: 5a + 5b scatter ----
    {
        const int jj = t & 63, egp = t >> 6;
        // 5a: s_out = (silu_s @ Wp_s) * w[:128] (paired k)
        {
            u64 a0[2] = {0,0}, a1[2] = {0,0};
#pragma unroll 4
            for (int k2 = 0; k2 < 64; k2++) {
                float4 w = w_psq[k2 * 64 + jj];
                ulonglong2 q0 = sO02[(2 * k2) * NQ2 + egp];
                ulonglong2 q1 = sO02[(2 * k2 + 1) * NQ2 + egp];
                u64 WA0 = pk2(w.x), WB0 = pk2(w.y), WA1 = pk2(w.z), WB1 = pk2(w.w);
                fma2(a0[0], q0.x, WA0); fma2(a0[1], q0.y, WA0);
                fma2(a1[0], q0.x, WB0); fma2(a1[1], q0.y, WB0);
                fma2(a0[0], q1.x, WA1); fma2(a0[1], q1.y, WA1);
                fma2(a1[0], q1.x, WB1); fma2(a1[1], q1.y, WB1);
            }
            float r0[4], r1[4];
            un4(a0, r0); un4(a1, r1);
#pragma unroll
            for (int s = 0; s < 4; s++) {
                int c = sC[egp * 4 + s];
                atomicAdd(&out[c * 320 + jj],      r0[s] * w0r[s] * 0.25f);
                atomicAdd(&out[c * 320 + 64 + jj], r1[s] * w1r[s] * 0.25f);
            }
        }
        // 5b: v_out = (v @ Wp_v) * w[128+f2] (quad kf)
        {
            u64 pVx[2]={0,0}, pVy[2]={0,0}, pVz[2]={0,0};
#pragma unroll 2
            for (int kk = 0; kk < 16; kk++) {
                float4 w = w_pvq[kk * 64 + jj];
#pragma unroll
                for (int s = 0; s < 4; s++) {
                    int kf = 4 * kk + s;
                    u64 W = pk2(((const float*)&w)[s]);
                    ulonglong2 vx = sOV2[(kf * 3 + 0) * NQ2 + egp];
                    ulonglong2 vy = sOV2[(kf * 3 + 1) * NQ2 + egp];
                    ulonglong2 vz = sOV2[(kf * 3 + 2) * NQ2 + egp];
                    fma2(pVx[0], vx.x, W); fma2(pVx[1], vx.y, W);
                    fma2(pVy[0], vy.x, W); fma2(pVy[1], vy.y, W);
                    fma2(pVz[0], vz.x, W); fma2(pVz[1], vz.y, W);
                }
            }
            float Vx[4], Vy[4], Vz[4];
            un4(pVx, Vx); un4(pVy, Vy); un4(pVz, Vz);
#pragma unroll
            for (int s = 0; s < 4; s++) {
                int c = sC[egp * 4 + s];
                float ww = w2r[s] * 0.25f;
                atomicAdd(&out[c * 320 + 128 + jj * 3 + 0], Vx[s] * ww);
                atomicAdd(&out[c * 320 + 128 + jj * 3 + 1], Vy[s] * ww);
                atomicAdd(&out[c * 320 + 128 + jj * 3 + 2], Vz[s] * ww);
            }
        }
    }
}

extern "C" void kernel_launch(void* const* d_in, const int* in_sizes, int n_in,
                              void* d_out, int out_size)
{
    const float* latents = (const float*)d_in[0];
    const float* nodef   = (const float*)d_in[1];
    const float* edgef   = (const float*)d_in[2];
    const float* esh     = (const float*)d_in[3];
    const int*   eidx    = (const int*)d_in[4];
    /* d_in[5] atom_type unused */
    const int*   act     = (const int*)d_in[6];
    const float* gsn  = (const float*)d_in[7];
    const float* bsn  = (const float*)d_in[8];
    const float* gvn  = (const float*)d_in[9];
    const float* gse  = (const float*)d_in[10];
    const float* bse  = (const float*)d_in[11];
    const float* gve  = (const float*)d_in[12];
    const float* Wss0 = (const float*)d_in[13];
    const float* Wvv0 = (const float*)d_in[14];
    const float* Wsv1 = (const float*)d_in[15];
    const float* Wvs1 = (const float*)d_in[16];
    const float* Wvv1 = (const float*)d_in[17];
    const float* Wps  = (const float*)d_in[18];
    const float* Wpv  = (const float*)d_in[19];
    const float* Wenv = (const float*)d_in[20];
    const float* Wrs  = (const float*)d_in[21];
    const float* Wrv  = (const float*)d_in[22];
    float* out = (float*)d_out;

    const size_t NODE_SMEM = (16384 + 4096 + 320 + 8) * sizeof(float);
    const size_t EDGE_SMEM = SMEM_EDGE_FLOATS * sizeof(float);

    cudaFuncSetAttribute(node_kernel, cudaFuncAttributeMaxDynamicSharedMemorySize,
                         (int)NODE_SMEM);
    cudaFuncSetAttribute(edge_kernel, cudaFuncAttributeMaxDynamicSharedMemorySize,
                         (int)EDGE_SMEM);

    node_kernel<<<424, 128, NODE_SMEM>>>(nodef, gsn, bsn, gvn, Wrs, Wrv,
                                         Wss0, Wvv0, Wenv, Wps, Wvs1, Wvv1,
                                         Wsv1, Wpv, out);
    edge_kernel<<<10000, 256, EDGE_SMEM>>>(latents, edgef, esh, eidx, act,
                                           gse, bse, gve, out);
}